// round 16
// baseline (speedup 1.0000x reference)
#include <cuda_runtime.h>
#include <cuda_fp16.h>
#include <math.h>
#include <stdint.h>

#define N_NODES 100000
#define N_EDGES 1600000
#define IN_DIM  256
#define OUT_DIM 64
#define LEAKY   0.01f

#define SCAN_CHUNK 1024
#define NCHUNKS ((N_NODES + SCAN_CHUNK - 1) / SCAN_CHUNK)   // 98

// ---------------- scratch (zero-initialized at module load) ----------------
__device__ __half2 g_zh [N_NODES * (OUT_DIM / 2)];  // 12.8 MB, 128B/row (L2-resident)
__device__ float   g_el [N_NODES];
__device__ float   g_er [N_NODES];
__device__ int     g_cnt[N_NODES];            // INVARIANT: zero at entry of each call
__device__ int     g_off[N_NODES + 1];        // chunk-local exclusive prefix
__device__ int     g_rank[N_EDGES];           // within-destination rank of each edge
__device__ int     g_bsum[NCHUNKS];           // global exclusive chunk prefix
__device__ int     g_csr[N_EDGES];            // src ids, dst-sorted
__device__ int     g_done;                    // scan1 completion counter (self-resetting)

// ---------------- helpers ----------------
__device__ __forceinline__ float cvt_tf32(float x) {
    uint32_t o;
    asm("cvt.rna.tf32.f32 %0, %1;" : "=r"(o) : "f"(x));
    return __uint_as_float(o);
}

__device__ __forceinline__ float4 cvt_tf32_v4(float4 v) {
    v.x = cvt_tf32(v.x); v.y = cvt_tf32(v.y);
    v.z = cvt_tf32(v.z); v.w = cvt_tf32(v.w);
    return v;
}

__device__ __forceinline__ void mma_tf32(float& d0, float& d1, float& d2, float& d3,
                                         uint32_t a0, uint32_t a1, uint32_t a2, uint32_t a3,
                                         uint32_t b0, uint32_t b1) {
    asm volatile("mma.sync.aligned.m16n8k8.row.col.f32.tf32.tf32.f32 "
                 "{%0,%1,%2,%3}, {%4,%5,%6,%7}, {%8,%9}, {%0,%1,%2,%3};"
                 : "+f"(d0), "+f"(d1), "+f"(d2), "+f"(d3)
                 : "r"(a0), "r"(a1), "r"(a2), "r"(a3), "r"(b0), "r"(b1));
}

// ---------------- K1: tensor-core GEMM + fused dst-histogram --------------------
__global__ void __launch_bounds__(256) k_gemm(const float* __restrict__ h,
                                              const float* __restrict__ W,
                                              const float* __restrict__ a_attn,
                                              const int* __restrict__ edst) {
    __shared__ float As[128][36];   // pad 36: conflict-free A frag loads
    __shared__ float Bs[32][72];    // pad 72: conflict-free B frag loads

    const int tid  = threadIdx.x;
    const int warp = tid >> 5;
    const int lane = tid & 31;
    const int m0   = blockIdx.x * 128;
    const int wrow = warp * 16;
    const int r = lane >> 2;        // 0..7
    const int c = lane & 3;         // 0..3

    int arow[4], akq[4];
#pragma unroll
    for (int i = 0; i < 4; i++) {
        int id = tid + i * 256;
        arow[i] = id >> 3;
        akq[i]  = id & 7;
    }
    int bkk[2], bnq[2];
#pragma unroll
    for (int i = 0; i < 2; i++) {
        int id = tid + i * 256;
        bkk[i] = id >> 4;
        bnq[i] = id & 15;
    }

    float d[8][4];
#pragma unroll
    for (int j = 0; j < 8; j++)
#pragma unroll
        for (int q = 0; q < 4; q++) d[j][q] = 0.0f;

    float4 ra[4], rb[2];

    // prologue: load chunk 0
#pragma unroll
    for (int i = 0; i < 4; i++) {
        float4 v = make_float4(0.f, 0.f, 0.f, 0.f);
        if (m0 + arow[i] < N_NODES)
            v = *(const float4*)(h + (size_t)(m0 + arow[i]) * IN_DIM + akq[i] * 4);
        ra[i] = cvt_tf32_v4(v);
    }
#pragma unroll
    for (int i = 0; i < 2; i++)
        rb[i] = cvt_tf32_v4(*(const float4*)(W + (size_t)bkk[i] * OUT_DIM + bnq[i] * 4));

    for (int k0 = 0; k0 < IN_DIM; k0 += 32) {
#pragma unroll
        for (int i = 0; i < 4; i++)
            *(float4*)&As[arow[i]][akq[i] * 4] = ra[i];
#pragma unroll
        for (int i = 0; i < 2; i++)
            *(float4*)&Bs[bkk[i]][bnq[i] * 4] = rb[i];
        __syncthreads();

        int kn = k0 + 32;
        if (kn < IN_DIM) {
#pragma unroll
            for (int i = 0; i < 4; i++) {
                float4 v = make_float4(0.f, 0.f, 0.f, 0.f);
                if (m0 + arow[i] < N_NODES)
                    v = *(const float4*)(h + (size_t)(m0 + arow[i]) * IN_DIM + kn + akq[i] * 4);
                ra[i] = cvt_tf32_v4(v);
            }
#pragma unroll
            for (int i = 0; i < 2; i++)
                rb[i] = cvt_tf32_v4(*(const float4*)(W + (size_t)(kn + bkk[i]) * OUT_DIM + bnq[i] * 4));
        }

#pragma unroll
        for (int ks = 0; ks < 32; ks += 8) {
            uint32_t a0 = __float_as_uint(As[wrow + r    ][ks + c    ]);
            uint32_t a1 = __float_as_uint(As[wrow + r + 8][ks + c    ]);
            uint32_t a2 = __float_as_uint(As[wrow + r    ][ks + c + 4]);
            uint32_t a3 = __float_as_uint(As[wrow + r + 8][ks + c + 4]);
#pragma unroll
            for (int j = 0; j < 8; j++) {
                uint32_t b0 = __float_as_uint(Bs[ks + c    ][8 * j + r]);
                uint32_t b1 = __float_as_uint(Bs[ks + c + 4][8 * j + r]);
                mma_tf32(d[j][0], d[j][1], d[j][2], d[j][3], a0, a1, a2, a3, b0, b1);
            }
        }
        __syncthreads();
    }

    // ---- epilogue: store z (fp16), compute el/er from fp32 accumulators ---------
    const int row_lo = m0 + wrow + r;
    const int row_hi = row_lo + 8;

    float pl0 = 0.f, pl1 = 0.f, pr0 = 0.f, pr1 = 0.f;
#pragma unroll
    for (int j = 0; j < 8; j++) {
        int n = 8 * j + 2 * c;
        float al0 = a_attn[n], al1 = a_attn[n + 1];
        float ar0 = a_attn[OUT_DIM + n], ar1 = a_attn[OUT_DIM + n + 1];
        pl0 += d[j][0] * al0 + d[j][1] * al1;
        pr0 += d[j][0] * ar0 + d[j][1] * ar1;
        pl1 += d[j][2] * al0 + d[j][3] * al1;
        pr1 += d[j][2] * ar0 + d[j][3] * ar1;
        if (row_lo < N_NODES)
            g_zh[(size_t)row_lo * 32 + (n >> 1)] = __floats2half2_rn(d[j][0], d[j][1]);
        if (row_hi < N_NODES)
            g_zh[(size_t)row_hi * 32 + (n >> 1)] = __floats2half2_rn(d[j][2], d[j][3]);
    }
#pragma unroll
    for (int o = 1; o <= 2; o <<= 1) {
        pl0 += __shfl_xor_sync(0xffffffffu, pl0, o);
        pl1 += __shfl_xor_sync(0xffffffffu, pl1, o);
        pr0 += __shfl_xor_sync(0xffffffffu, pr0, o);
        pr1 += __shfl_xor_sync(0xffffffffu, pr1, o);
    }
    if (c == 0) {
        if (row_lo < N_NODES) { g_el[row_lo] = pl0; g_er[row_lo] = pr0; }
        if (row_hi < N_NODES) { g_el[row_hi] = pl1; g_er[row_hi] = pr1; }
    }

    // ---- fused dst-histogram + rank capture (g_cnt is 0 by pipeline invariant) --
    {
        const int T = gridDim.x * 256;
        for (int e = blockIdx.x * 256 + tid; e < N_EDGES; e += T) {
            g_rank[e] = atomicAdd(&g_cnt[edst[e]], 1);
        }
    }
}

// ---------------- K2: per-chunk scan; last-arriving block scans chunk totals ----
__global__ void __launch_bounds__(SCAN_CHUNK) k_scan1() {
    __shared__ int wsum[32];
    __shared__ int sh[128];
    __shared__ int amLast;
    const int tid  = threadIdx.x;
    const int lane = tid & 31;
    const int w    = tid >> 5;
    const int i    = blockIdx.x * SCAN_CHUNK + tid;

    int x = (i < N_NODES) ? g_cnt[i] : 0;
    int v = x;
#pragma unroll
    for (int o = 1; o < 32; o <<= 1) {
        int t = __shfl_up_sync(0xffffffffu, v, o);
        if (lane >= o) v += t;
    }
    if (lane == 31) wsum[w] = v;
    __syncthreads();
    if (w == 0) {
        int y = wsum[lane];
#pragma unroll
        for (int o = 1; o < 32; o <<= 1) {
            int t = __shfl_up_sync(0xffffffffu, y, o);
            if (lane >= o) y += t;
        }
        wsum[lane] = y;   // inclusive warp sums
    }
    __syncthreads();
    int base = (w > 0) ? wsum[w - 1] : 0;
    int incl = v + base;
    if (i < N_NODES) g_off[i] = incl - x;          // chunk-local exclusive
    if (tid == SCAN_CHUNK - 1) g_bsum[blockIdx.x] = incl;  // chunk total

    // ---- last arriving block scans the 98 chunk totals (no spinning) ----
    __threadfence();
    if (tid == 0) amLast = (atomicAdd(&g_done, 1) == NCHUNKS - 1);
    __syncthreads();
    if (amLast) {
        int xx = (tid < NCHUNKS) ? g_bsum[tid] : 0;
        if (tid < 128) sh[tid] = xx;
        __syncthreads();
#pragma unroll
        for (int off = 1; off < 128; off <<= 1) {
            int t = (tid < 128 && tid >= off) ? sh[tid - off] : 0;
            __syncthreads();
            if (tid < 128) sh[tid] += t;
            __syncthreads();
        }
        if (tid < NCHUNKS) g_bsum[tid] = sh[tid] - xx;   // global exclusive chunk prefix
        if (tid == 0) { g_off[N_NODES] = N_EDGES; g_done = 0; }
    }
}

// ---------------- K3: atomic-free scatter (bsum folded) + g_cnt re-zero ---------
__global__ void k_scatter(const int* __restrict__ src, const int* __restrict__ dst) {
    int i2 = blockIdx.x * blockDim.x + threadIdx.x;   // pair index
    // restore pipeline invariant for the next call (g_cnt dead after scan1)
    if (i2 < N_NODES) g_cnt[i2] = 0;
    int i = i2 * 2;
    if (i >= N_EDGES) return;
    // N_EDGES is even; full pairs everywhere
    int2 sv = *(const int2*)(src + i);
    int2 dv = *(const int2*)(dst + i);
    int2 rv = *(const int2*)(g_rank + i);
    g_csr[g_off[dv.x] + g_bsum[dv.x >> 10] + rv.x] = sv.x;
    g_csr[g_off[dv.y] + g_bsum[dv.y >> 10] + rv.y] = sv.y;
}

// ---------------- K4: single-pass softmax + fp16 gather + ELU (4-lane groups) ---
// 4 lanes per dst node; each lane gathers 32B (2 x uint4) of the 128B fp16 z row.
__global__ void __launch_bounds__(256) k_aggr(float* __restrict__ out) {
    const int gid  = blockIdx.x * blockDim.x + threadIdx.x;
    const int node = gid >> 2;
    if (node >= N_NODES) return;
    const int lane  = threadIdx.x & 31;
    const int l     = lane & 3;                     // lane within 4-group
    const int sbase = lane & 28;                    // 4 * (group index in warp)
    const unsigned gmask = 0xFu << sbase;           // group mask

    const int beg = g_off[node] + g_bsum[node >> 10];
    const int np1 = node + 1;
    const int end = (np1 == N_NODES) ? N_EDGES : (g_off[np1] + g_bsum[np1 >> 10]);
    const float erd = g_er[node];

    float s = 0.0f;
    float acc[16];
#pragma unroll
    for (int q = 0; q < 16; q++) acc[q] = 0.0f;

    for (int j0 = beg; j0 < end; j0 += 4) {
        int j = j0 + l;
        int sn = 0;
        float ax = 0.0f;
        if (j < end) {
            sn = g_csr[j];
            float e = __ldg(&g_el[sn]) + erd;
            e = (e >= 0.0f) ? e : LEAKY * e;
            ax = __expf(e);
            s += ax;
        }
        int cnt = min(4, end - j0);
#pragma unroll 4
        for (int t = 0; t < cnt; t++) {
            int   sj = __shfl_sync(gmask, sn, sbase + t);
            float aj = __shfl_sync(gmask, ax, sbase + t);
            // fp16 row: 128B = 8 x uint4; lane l loads 32B (cols 16l..16l+15)
            const uint4* zp = ((const uint4*)(g_zh + (size_t)sj * 32)) + 2 * l;
            uint4 r0 = __ldg(zp);
            uint4 r1 = __ldg(zp + 1);
            float2 f0 = __half22float2(*reinterpret_cast<__half2*>(&r0.x));
            float2 f1 = __half22float2(*reinterpret_cast<__half2*>(&r0.y));
            float2 f2 = __half22float2(*reinterpret_cast<__half2*>(&r0.z));
            float2 f3 = __half22float2(*reinterpret_cast<__half2*>(&r0.w));
            acc[0]  += aj * f0.x; acc[1]  += aj * f0.y;
            acc[2]  += aj * f1.x; acc[3]  += aj * f1.y;
            acc[4]  += aj * f2.x; acc[5]  += aj * f2.y;
            acc[6]  += aj * f3.x; acc[7]  += aj * f3.y;
            float2 g0 = __half22float2(*reinterpret_cast<__half2*>(&r1.x));
            float2 g1 = __half22float2(*reinterpret_cast<__half2*>(&r1.y));
            float2 g2 = __half22float2(*reinterpret_cast<__half2*>(&r1.z));
            float2 g3 = __half22float2(*reinterpret_cast<__half2*>(&r1.w));
            acc[8]  += aj * g0.x; acc[9]  += aj * g0.y;
            acc[10] += aj * g1.x; acc[11] += aj * g1.y;
            acc[12] += aj * g2.x; acc[13] += aj * g2.y;
            acc[14] += aj * g3.x; acc[15] += aj * g3.y;
        }
    }

    // reduce s across the 4-lane group
#pragma unroll
    for (int o = 2; o; o >>= 1)
        s += __shfl_xor_sync(gmask, s, o);
    float rs = (s > 0.0f) ? (1.0f / s) : 0.0f;

#pragma unroll
    for (int q = 0; q < 16; q++) {
        float v = acc[q] * rs;
        acc[q] = (v > 0.0f) ? v : expm1f(v);
    }

    // lane l owns cols 16l..16l+15 of the output row: four float4 stores
    float* op = out + (size_t)node * OUT_DIM + l * 16;
    *(float4*)(op     ) = make_float4(acc[0],  acc[1],  acc[2],  acc[3]);
    *(float4*)(op +  4) = make_float4(acc[4],  acc[5],  acc[6],  acc[7]);
    *(float4*)(op +  8) = make_float4(acc[8],  acc[9],  acc[10], acc[11]);
    *(float4*)(op + 12) = make_float4(acc[12], acc[13], acc[14], acc[15]);
}

// ---------------- launch ----------------
extern "C" void kernel_launch(void* const* d_in, const int* in_sizes, int n_in,
                              void* d_out, int out_size) {
    const float* h      = (const float*)d_in[0];
    const float* W_fc   = (const float*)d_in[1];
    const float* a_attn = (const float*)d_in[2];
    const int*   e_src  = (const int*)d_in[3];
    const int*   e_dst  = (const int*)d_in[4];
    float* out = (float*)d_out;

    k_gemm<<<(N_NODES + 127) / 128, 256>>>(h, W_fc, a_attn, e_dst);
    k_scan1<<<NCHUNKS, SCAN_CHUNK>>>();
    k_scatter<<<(N_EDGES / 2 + 255) / 256, 256>>>(e_src, e_dst);
    k_aggr<<<(N_NODES * 4 + 255) / 256, 256>>>(out);
}

// round 17
// speedup vs baseline: 1.0311x; 1.0311x over previous
#include <cuda_runtime.h>
#include <cuda_fp16.h>
#include <math.h>
#include <stdint.h>

#define N_NODES 100000
#define N_EDGES 1600000
#define IN_DIM  256
#define OUT_DIM 64
#define LEAKY   0.01f

#define SCAN_CHUNK 1024
#define NCHUNKS ((N_NODES + SCAN_CHUNK - 1) / SCAN_CHUNK)   // 98

// ---------------- scratch (zero-initialized at module load) ----------------
__device__ __half2 g_zh [N_NODES * (OUT_DIM / 2)];  // 12.8 MB, 128B/row (L2-resident)
__device__ float   g_el [N_NODES];
__device__ float   g_er [N_NODES];
__device__ int     g_cnt[N_NODES];            // INVARIANT: zero at entry of each call
__device__ int     g_off[N_NODES + 1];        // chunk-local exclusive prefix
__device__ int     g_rank[N_EDGES];           // within-destination rank of each edge
__device__ int     g_bsum[NCHUNKS];           // global exclusive chunk prefix
__device__ int     g_csr[N_EDGES];            // src ids, dst-sorted
__device__ int     g_done;                    // scan1 completion counter (self-resetting)

// ---------------- helpers ----------------
__device__ __forceinline__ float cvt_tf32(float x) {
    uint32_t o;
    asm("cvt.rna.tf32.f32 %0, %1;" : "=r"(o) : "f"(x));
    return __uint_as_float(o);
}

__device__ __forceinline__ float4 cvt_tf32_v4(float4 v) {
    v.x = cvt_tf32(v.x); v.y = cvt_tf32(v.y);
    v.z = cvt_tf32(v.z); v.w = cvt_tf32(v.w);
    return v;
}

__device__ __forceinline__ void mma_tf32(float& d0, float& d1, float& d2, float& d3,
                                         uint32_t a0, uint32_t a1, uint32_t a2, uint32_t a3,
                                         uint32_t b0, uint32_t b1) {
    asm volatile("mma.sync.aligned.m16n8k8.row.col.f32.tf32.tf32.f32 "
                 "{%0,%1,%2,%3}, {%4,%5,%6,%7}, {%8,%9}, {%0,%1,%2,%3};"
                 : "+f"(d0), "+f"(d1), "+f"(d2), "+f"(d3)
                 : "r"(a0), "r"(a1), "r"(a2), "r"(a3), "r"(b0), "r"(b1));
}

// ---------------- K1: tensor-core GEMM + fused dst-histogram --------------------
__global__ void __launch_bounds__(256) k_gemm(const float* __restrict__ h,
                                              const float* __restrict__ W,
                                              const float* __restrict__ a_attn,
                                              const int* __restrict__ edst) {
    __shared__ float As[128][36];   // pad 36: conflict-free A frag loads
    __shared__ float Bs[32][72];    // pad 72: conflict-free B frag loads

    const int tid  = threadIdx.x;
    const int warp = tid >> 5;
    const int lane = tid & 31;
    const int m0   = blockIdx.x * 128;
    const int wrow = warp * 16;
    const int r = lane >> 2;        // 0..7
    const int c = lane & 3;         // 0..3

    int arow[4], akq[4];
#pragma unroll
    for (int i = 0; i < 4; i++) {
        int id = tid + i * 256;
        arow[i] = id >> 3;
        akq[i]  = id & 7;
    }
    int bkk[2], bnq[2];
#pragma unroll
    for (int i = 0; i < 2; i++) {
        int id = tid + i * 256;
        bkk[i] = id >> 4;
        bnq[i] = id & 15;
    }

    float d[8][4];
#pragma unroll
    for (int j = 0; j < 8; j++)
#pragma unroll
        for (int q = 0; q < 4; q++) d[j][q] = 0.0f;

    float4 ra[4], rb[2];

    // prologue: load chunk 0
#pragma unroll
    for (int i = 0; i < 4; i++) {
        float4 v = make_float4(0.f, 0.f, 0.f, 0.f);
        if (m0 + arow[i] < N_NODES)
            v = *(const float4*)(h + (size_t)(m0 + arow[i]) * IN_DIM + akq[i] * 4);
        ra[i] = cvt_tf32_v4(v);
    }
#pragma unroll
    for (int i = 0; i < 2; i++)
        rb[i] = cvt_tf32_v4(*(const float4*)(W + (size_t)bkk[i] * OUT_DIM + bnq[i] * 4));

    for (int k0 = 0; k0 < IN_DIM; k0 += 32) {
#pragma unroll
        for (int i = 0; i < 4; i++)
            *(float4*)&As[arow[i]][akq[i] * 4] = ra[i];
#pragma unroll
        for (int i = 0; i < 2; i++)
            *(float4*)&Bs[bkk[i]][bnq[i] * 4] = rb[i];
        __syncthreads();

        int kn = k0 + 32;
        if (kn < IN_DIM) {
#pragma unroll
            for (int i = 0; i < 4; i++) {
                float4 v = make_float4(0.f, 0.f, 0.f, 0.f);
                if (m0 + arow[i] < N_NODES)
                    v = *(const float4*)(h + (size_t)(m0 + arow[i]) * IN_DIM + kn + akq[i] * 4);
                ra[i] = cvt_tf32_v4(v);
            }
#pragma unroll
            for (int i = 0; i < 2; i++)
                rb[i] = cvt_tf32_v4(*(const float4*)(W + (size_t)(kn + bkk[i]) * OUT_DIM + bnq[i] * 4));
        }

#pragma unroll
        for (int ks = 0; ks < 32; ks += 8) {
            uint32_t a0 = __float_as_uint(As[wrow + r    ][ks + c    ]);
            uint32_t a1 = __float_as_uint(As[wrow + r + 8][ks + c    ]);
            uint32_t a2 = __float_as_uint(As[wrow + r    ][ks + c + 4]);
            uint32_t a3 = __float_as_uint(As[wrow + r + 8][ks + c + 4]);
#pragma unroll
            for (int j = 0; j < 8; j++) {
                uint32_t b0 = __float_as_uint(Bs[ks + c    ][8 * j + r]);
                uint32_t b1 = __float_as_uint(Bs[ks + c + 4][8 * j + r]);
                mma_tf32(d[j][0], d[j][1], d[j][2], d[j][3], a0, a1, a2, a3, b0, b1);
            }
        }
        __syncthreads();
    }

    // ---- epilogue: store z (fp16), compute el/er from fp32 accumulators ---------
    const int row_lo = m0 + wrow + r;
    const int row_hi = row_lo + 8;

    float pl0 = 0.f, pl1 = 0.f, pr0 = 0.f, pr1 = 0.f;
#pragma unroll
    for (int j = 0; j < 8; j++) {
        int n = 8 * j + 2 * c;
        float al0 = a_attn[n], al1 = a_attn[n + 1];
        float ar0 = a_attn[OUT_DIM + n], ar1 = a_attn[OUT_DIM + n + 1];
        pl0 += d[j][0] * al0 + d[j][1] * al1;
        pr0 += d[j][0] * ar0 + d[j][1] * ar1;
        pl1 += d[j][2] * al0 + d[j][3] * al1;
        pr1 += d[j][2] * ar0 + d[j][3] * ar1;
        if (row_lo < N_NODES)
            g_zh[(size_t)row_lo * 32 + (n >> 1)] = __floats2half2_rn(d[j][0], d[j][1]);
        if (row_hi < N_NODES)
            g_zh[(size_t)row_hi * 32 + (n >> 1)] = __floats2half2_rn(d[j][2], d[j][3]);
    }
#pragma unroll
    for (int o = 1; o <= 2; o <<= 1) {
        pl0 += __shfl_xor_sync(0xffffffffu, pl0, o);
        pl1 += __shfl_xor_sync(0xffffffffu, pl1, o);
        pr0 += __shfl_xor_sync(0xffffffffu, pr0, o);
        pr1 += __shfl_xor_sync(0xffffffffu, pr1, o);
    }
    if (c == 0) {
        if (row_lo < N_NODES) { g_el[row_lo] = pl0; g_er[row_lo] = pr0; }
        if (row_hi < N_NODES) { g_el[row_hi] = pl1; g_er[row_hi] = pr1; }
    }

    // ---- fused dst-histogram + rank capture (g_cnt is 0 by pipeline invariant) --
    {
        const int T = gridDim.x * 256;
        for (int e = blockIdx.x * 256 + tid; e < N_EDGES; e += T) {
            g_rank[e] = atomicAdd(&g_cnt[edst[e]], 1);
        }
    }
}

// ---------------- K2: per-chunk scan; last-arriving block scans chunk totals ----
__global__ void __launch_bounds__(SCAN_CHUNK) k_scan1() {
    __shared__ int wsum[32];
    __shared__ int sh[128];
    __shared__ int amLast;
    const int tid  = threadIdx.x;
    const int lane = tid & 31;
    const int w    = tid >> 5;
    const int i    = blockIdx.x * SCAN_CHUNK + tid;

    int x = (i < N_NODES) ? g_cnt[i] : 0;
    int v = x;
#pragma unroll
    for (int o = 1; o < 32; o <<= 1) {
        int t = __shfl_up_sync(0xffffffffu, v, o);
        if (lane >= o) v += t;
    }
    if (lane == 31) wsum[w] = v;
    __syncthreads();
    if (w == 0) {
        int y = wsum[lane];
#pragma unroll
        for (int o = 1; o < 32; o <<= 1) {
            int t = __shfl_up_sync(0xffffffffu, y, o);
            if (lane >= o) y += t;
        }
        wsum[lane] = y;   // inclusive warp sums
    }
    __syncthreads();
    int base = (w > 0) ? wsum[w - 1] : 0;
    int incl = v + base;
    if (i < N_NODES) g_off[i] = incl - x;          // chunk-local exclusive
    if (tid == SCAN_CHUNK - 1) g_bsum[blockIdx.x] = incl;  // chunk total

    // ---- last arriving block scans the 98 chunk totals (no spinning) ----
    __threadfence();
    if (tid == 0) amLast = (atomicAdd(&g_done, 1) == NCHUNKS - 1);
    __syncthreads();
    if (amLast) {
        int xx = (tid < NCHUNKS) ? g_bsum[tid] : 0;
        if (tid < 128) sh[tid] = xx;
        __syncthreads();
#pragma unroll
        for (int off = 1; off < 128; off <<= 1) {
            int t = (tid < 128 && tid >= off) ? sh[tid - off] : 0;
            __syncthreads();
            if (tid < 128) sh[tid] += t;
            __syncthreads();
        }
        if (tid < NCHUNKS) g_bsum[tid] = sh[tid] - xx;   // global exclusive chunk prefix
        if (tid == 0) { g_off[N_NODES] = N_EDGES; g_done = 0; }
    }
}

// ---------------- K3: atomic-free scatter (bsum folded) + g_cnt re-zero ---------
__global__ void k_scatter(const int* __restrict__ src, const int* __restrict__ dst) {
    int i2 = blockIdx.x * blockDim.x + threadIdx.x;   // pair index
    // restore pipeline invariant for the next call (g_cnt dead after scan1)
    if (i2 < N_NODES) g_cnt[i2] = 0;
    int i = i2 * 2;
    if (i >= N_EDGES) return;
    // N_EDGES is even; full pairs everywhere
    int2 sv = *(const int2*)(src + i);
    int2 dv = *(const int2*)(dst + i);
    int2 rv = *(const int2*)(g_rank + i);
    g_csr[g_off[dv.x] + g_bsum[dv.x >> 10] + rv.x] = sv.x;
    g_csr[g_off[dv.y] + g_bsum[dv.y >> 10] + rv.y] = sv.y;
}

// ---------------- K4: single-pass softmax + fp16 gather + ELU (8-lane groups) ---
// 8 lanes per dst node; each lane gathers 16B (uint4) of the 128B fp16 z row.
// Measured optimum lane width (16->8 good, 8->4 regressed).
__global__ void __launch_bounds__(256) k_aggr(float* __restrict__ out) {
    const int gid  = blockIdx.x * blockDim.x + threadIdx.x;
    const int node = gid >> 3;
    if (node >= N_NODES) return;
    const int lane  = threadIdx.x & 31;
    const int l     = lane & 7;                     // lane within 8-group
    const int sbase = lane & 24;                    // 8 * (group index in warp)
    const unsigned gmask = 0xFFu << sbase;          // group mask

    const int beg = g_off[node] + g_bsum[node >> 10];
    const int np1 = node + 1;
    const int end = (np1 == N_NODES) ? N_EDGES : (g_off[np1] + g_bsum[np1 >> 10]);
    const float erd = g_er[node];

    float s = 0.0f;
    float acc[8];
#pragma unroll
    for (int q = 0; q < 8; q++) acc[q] = 0.0f;

    for (int j0 = beg; j0 < end; j0 += 8) {
        int j = j0 + l;
        int sn = 0;
        float ax = 0.0f;
        if (j < end) {
            sn = g_csr[j];
            float e = __ldg(&g_el[sn]) + erd;
            e = (e >= 0.0f) ? e : LEAKY * e;
            ax = __expf(e);
            s += ax;
        }
        int cnt = min(8, end - j0);
#pragma unroll 4
        for (int t = 0; t < cnt; t++) {
            int   sj = __shfl_sync(gmask, sn, sbase + t);
            float aj = __shfl_sync(gmask, ax, sbase + t);
            // fp16 row: 128B = 8 x uint4; lane l loads 16B (cols 8l..8l+7)
            uint4 raw = __ldg(((const uint4*)(g_zh + (size_t)sj * 32)) + l);
            float2 f0 = __half22float2(*reinterpret_cast<__half2*>(&raw.x));
            float2 f1 = __half22float2(*reinterpret_cast<__half2*>(&raw.y));
            float2 f2 = __half22float2(*reinterpret_cast<__half2*>(&raw.z));
            float2 f3 = __half22float2(*reinterpret_cast<__half2*>(&raw.w));
            acc[0] += aj * f0.x; acc[1] += aj * f0.y;
            acc[2] += aj * f1.x; acc[3] += aj * f1.y;
            acc[4] += aj * f2.x; acc[5] += aj * f2.y;
            acc[6] += aj * f3.x; acc[7] += aj * f3.y;
        }
    }

    // reduce s across the 8-lane group
#pragma unroll
    for (int o = 4; o; o >>= 1)
        s += __shfl_xor_sync(gmask, s, o);
    float rs = (s > 0.0f) ? (1.0f / s) : 0.0f;

#pragma unroll
    for (int q = 0; q < 8; q++) {
        float v = acc[q] * rs;
        acc[q] = (v > 0.0f) ? v : expm1f(v);
    }

    // lane l owns cols 8l..8l+7 of the output row: two float4 stores
    float* op = out + (size_t)node * OUT_DIM + l * 8;
    *(float4*)(op    ) = make_float4(acc[0], acc[1], acc[2], acc[3]);
    *(float4*)(op + 4) = make_float4(acc[4], acc[5], acc[6], acc[7]);
}

// ---------------- launch ----------------
extern "C" void kernel_launch(void* const* d_in, const int* in_sizes, int n_in,
                              void* d_out, int out_size) {
    const float* h      = (const float*)d_in[0];
    const float* W_fc   = (const float*)d_in[1];
    const float* a_attn = (const float*)d_in[2];
    const int*   e_src  = (const int*)d_in[3];
    const int*   e_dst  = (const int*)d_in[4];
    float* out = (float*)d_out;

    k_gemm<<<(N_NODES + 127) / 128, 256>>>(h, W_fc, a_attn, e_dst);
    k_scan1<<<NCHUNKS, SCAN_CHUNK>>>();
    k_scatter<<<(N_EDGES / 2 + 255) / 256, 256>>>(e_src, e_dst);
    k_aggr<<<(N_NODES * 8 + 255) / 256, 256>>>(out);
}